// round 5
// baseline (speedup 1.0000x reference)
#include <cuda_runtime.h>

// 3x3 VALID conv, stride 1, fp32.
// x: (64, 224, 224), kernels: (128, 64, 3, 3) -> out: (128, 222, 222)

#define C_IN   64
#define H_IN   224
#define W_IN   224
#define C_OUT  128
#define OH     222
#define OW     222

#define CSTEP   4      // input channels staged per sync round
#define TILE_H  4
#define TILE_W  32
#define PATCH_H 6      // TILE_H + 2
#define PATCH_W 34     // TILE_W + 2
#define PATCH_WS 36    // padded stride to dodge bank conflicts

__global__ __launch_bounds__(256, 2)
void conv3x3_direct_kernel(const float* __restrict__ x,
                           const float* __restrict__ wts,
                           float* __restrict__ out)
{
    __shared__ float sIn[CSTEP][PATCH_H][PATCH_WS];
    __shared__ float sW[CSTEP][C_OUT][9];

    const int tid = threadIdx.x;
    const int w0  = blockIdx.x * TILE_W;   // output col base
    const int h0  = blockIdx.y * TILE_H;   // output row base

    // thread -> (oc group, spatial strip)
    const int g  = tid >> 4;        // 0..15 : oc_base = g*8
    const int s  = tid & 15;        // 0..15
    const int r  = s >> 2;          // 0..3 : row within tile
    const int cc = (s & 3) * 8;     // 0,8,16,24 : col chunk within tile

    float acc[8][8];
    #pragma unroll
    for (int i = 0; i < 8; i++)
        #pragma unroll
        for (int j = 0; j < 8; j++)
            acc[i][j] = 0.0f;

    for (int c0 = 0; c0 < C_IN; c0 += CSTEP) {
        __syncthreads();   // protect previous stage's smem from overwrite

        // ---- stage input patch: CSTEP * 6 * 34 = 816 elems ----
        for (int t = tid; t < CSTEP * PATCH_H * PATCH_W; t += 256) {
            int ci  = t / (PATCH_H * PATCH_W);
            int rem = t - ci * (PATCH_H * PATCH_W);
            int ry  = rem / PATCH_W;
            int cx  = rem - ry * PATCH_W;
            int gh = h0 + ry;
            int gw = w0 + cx;
            float v = 0.0f;
            if (gh < H_IN && gw < W_IN)
                v = x[((c0 + ci) * H_IN + gh) * W_IN + gw];
            sIn[ci][ry][cx] = v;
        }

        // ---- stage weights: CSTEP * 128 * 9 = 4608 elems ----
        for (int t = tid; t < CSTEP * C_OUT * 9; t += 256) {
            int ci  = t / (C_OUT * 9);
            int rem = t - ci * (C_OUT * 9);
            int oc  = rem / 9;
            int k   = rem - oc * 9;
            sW[ci][oc][k] = wts[(oc * C_IN + (c0 + ci)) * 9 + k];
        }

        __syncthreads();

        // ---- compute ----
        #pragma unroll
        for (int ci = 0; ci < CSTEP; ci++) {
            // register-cache the 3x10 input window for this thread's strip
            float xv[3][10];
            #pragma unroll
            for (int dy = 0; dy < 3; dy++)
                #pragma unroll
                for (int dx = 0; dx < 10; dx++)
                    xv[dy][dx] = sIn[ci][r + dy][cc + dx];

            #pragma unroll
            for (int i = 0; i < 8; i++) {
                float wv[9];
                #pragma unroll
                for (int k = 0; k < 9; k++)
                    wv[k] = sW[ci][g * 8 + i][k];   // warp-broadcast LDS

                #pragma unroll
                for (int j = 0; j < 8; j++) {
                    float a = acc[i][j];
                    a = fmaf(wv[0], xv[0][j    ], a);
                    a = fmaf(wv[1], xv[0][j + 1], a);
                    a = fmaf(wv[2], xv[0][j + 2], a);
                    a = fmaf(wv[3], xv[1][j    ], a);
                    a = fmaf(wv[4], xv[1][j + 1], a);
                    a = fmaf(wv[5], xv[1][j + 2], a);
                    a = fmaf(wv[6], xv[2][j    ], a);
                    a = fmaf(wv[7], xv[2][j + 1], a);
                    a = fmaf(wv[8], xv[2][j + 2], a);
                    acc[i][j] = a;
                }
            }
        }
    }

    // ---- store ----
    const int oh = h0 + r;
    if (oh < OH) {
        #pragma unroll
        for (int i = 0; i < 8; i++) {
            int oc = g * 8 + i;
            float* orow = out + (oc * OH + oh) * OW;
            #pragma unroll
            for (int j = 0; j < 8; j++) {
                int ow = w0 + cc + j;
                if (ow < OW)
                    orow[ow] = acc[i][j];
            }
        }
    }
}

extern "C" void kernel_launch(void* const* d_in, const int* in_sizes, int n_in,
                              void* d_out, int out_size)
{
    const float* x = (const float*)d_in[0];
    const float* k = (const float*)d_in[1];
    // robustness: identify tensors by element count
    // x = 64*224*224 = 3211264, kernels = 128*64*3*3 = 73728
    if (in_sizes[0] == 73728) {
        const float* t = x; x = k; k = t;
    }
    float* out = (float*)d_out;

    dim3 grid((OW + TILE_W - 1) / TILE_W,   // 7
              (OH + TILE_H - 1) / TILE_H);  // 56
    conv3x3_direct_kernel<<<grid, 256>>>(x, k, out);
}

// round 10
// speedup vs baseline: 1.8468x; 1.8468x over previous
#include <cuda_runtime.h>
#include <cstdint>

// 3x3 VALID conv via implicit GEMM on mma.sync tf32 (3xTF32 split for accuracy).
// x: (64, 224, 224) fp32, kernels: (128, 64, 3, 3) -> out: (128, 222, 222)

#define C_IN   64
#define H_IN   224
#define W_IN   224
#define HW_IN  (H_IN * W_IN)
#define C_OUT  128
#define OH     222
#define OW     222
#define GK     576           // K = C_IN * 9

// ---------------- scratch globals (alloc-free rule) ----------------
__device__ float g_xhi[HW_IN * C_IN];   // NHWC, tf32-rounded hi
__device__ float g_xlo[HW_IN * C_IN];   // residual lo (tf32-rounded)
__device__ float g_whi[C_OUT * GK];     // [oc][(dy*3+dx)*64 + c]
__device__ float g_wlo[C_OUT * GK];

__device__ __forceinline__ void tf32_split(float v, float& hi, float& lo) {
    uint32_t hb;
    asm("cvt.rna.tf32.f32 %0, %1;" : "=r"(hb) : "f"(v));
    hi = __uint_as_float(hb);
    float r = v - hi;
    uint32_t lb;
    asm("cvt.rna.tf32.f32 %0, %1;" : "=r"(lb) : "f"(r));
    lo = __uint_as_float(lb);
}

// ---------------- prep kernels ----------------
__global__ void prep_x(const float* __restrict__ x) {
    __shared__ float s[64][65];
    int p0 = blockIdx.x * 64;
    for (int i = threadIdx.x; i < 64 * 64; i += 256) {
        int c = i >> 6, j = i & 63;
        s[c][j] = x[c * HW_IN + p0 + j];
    }
    __syncthreads();
    for (int i = threadIdx.x; i < 64 * 64; i += 256) {
        int j = i >> 6, c = i & 63;
        float hi, lo;
        tf32_split(s[c][j], hi, lo);
        g_xhi[(p0 + j) * 64 + c] = hi;
        g_xlo[(p0 + j) * 64 + c] = lo;
    }
}

__global__ void prep_w(const float* __restrict__ w) {
    int i = blockIdx.x * 256 + threadIdx.x;
    if (i < C_OUT * GK) {
        int oc = i / GK, r = i - oc * GK;
        int blk = r >> 6, c = r & 63;          // blk = dy*3+dx
        float hi, lo;
        tf32_split(w[oc * GK + c * 9 + blk], hi, lo);
        g_whi[i] = hi;
        g_wlo[i] = lo;
    }
}

// ---------------- main GEMM kernel ----------------
// CTA: 256 thr / 8 warps, tile M=128 x N=112. Warp grid 4(M) x 2(N) -> 32x56.
// K chunk = 16 floats. Smem rows hold interleaved hi/lo:
//   pos(k, which) = 16*(k>>3) + 4*(k&3) + 2*((k>>2)&1) + which
// so float4 at [row][kk*16 + 4*c] = {hi(c), lo(c), hi(c+4), lo(c+4)}.
#define SROW 48   // padded row stride (floats): conflict-free LDS.128 phases

__device__ __forceinline__ void mma_tf32(float* c, uint32_t a0, uint32_t a1,
                                         uint32_t a2, uint32_t a3,
                                         uint32_t b0, uint32_t b1) {
    asm volatile(
        "mma.sync.aligned.m16n8k8.row.col.f32.tf32.tf32.f32 "
        "{%0,%1,%2,%3}, {%4,%5,%6,%7}, {%8,%9}, {%0,%1,%2,%3};"
        : "+f"(c[0]), "+f"(c[1]), "+f"(c[2]), "+f"(c[3])
        : "r"(a0), "r"(a1), "r"(a2), "r"(a3), "r"(b0), "r"(b1));
}

__global__ void __launch_bounds__(256, 2)
conv_mma_tf32(float* __restrict__ out) {
    __shared__ float sA[128][SROW];   // weights chunk (hi/lo interleaved)
    __shared__ float sB[112][SROW];   // im2col chunk

    const int tid  = threadIdx.x;
    const int lane = tid & 31;
    const int wid  = tid >> 5;
    const int wm   = wid & 3;          // 0..3 -> M base 32*wm
    const int wn   = wid >> 2;         // 0..1 -> N base 56*wn
    const int h    = blockIdx.y;       // output row
    const int w0   = blockIdx.x * 112; // output col base

    const int rA  = lane >> 2;         // 0..7
    const int cA4 = (lane & 3) * 4;    // float4 offset within frag group

    float acc[2][7][4];
    #pragma unroll
    for (int mt = 0; mt < 2; mt++)
        #pragma unroll
        for (int nt = 0; nt < 7; nt++)
            #pragma unroll
            for (int q = 0; q < 4; q++)
                acc[mt][nt][q] = 0.0f;

    for (int t = 0; t < GK / 16; t++) {          // 36 chunks
        const int blk = t >> 2;                  // dy*3+dx
        const int dy  = blk / 3, dx = blk - dy * 3;
        const int off = (t & 3) * 16;            // channel offset within block

        __syncthreads();

        // ---- stage A: 128 rows x 16 k (hi+lo) ----
        for (int u = tid; u < 512; u += 256) {
            int row = u >> 2, q = u & 3;
            const float* gh = g_whi + row * GK + t * 16 + q * 4;
            const float* gl = g_wlo + row * GK + t * 16 + q * 4;
            float4 vh = *(const float4*)gh;
            float4 vl = *(const float4*)gl;
            float* dst = &sA[row][16 * (q >> 1) + 2 * (q & 1)];
            dst[0]  = vh.x; dst[1]  = vl.x;
            dst[4]  = vh.y; dst[5]  = vl.y;
            dst[8]  = vh.z; dst[9]  = vl.z;
            dst[12] = vh.w; dst[13] = vl.w;
        }

        // ---- stage B: 112 rows x 16 k (hi+lo) ----
        {
            const int rowStride = W_IN * 64;
            const float* xh = g_xhi + (h + dy) * rowStride + off;
            const float* xl = g_xlo + (h + dy) * rowStride + off;
            for (int u = tid; u < 448; u += 256) {
                int n = u >> 2, q = u & 3;
                int wc = w0 + n + dx; if (wc > W_IN - 1) wc = W_IN - 1;
                float4 vh = *(const float4*)(xh + wc * 64 + q * 4);
                float4 vl = *(const float4*)(xl + wc * 64 + q * 4);
                float* dst = &sB[n][16 * (q >> 1) + 2 * (q & 1)];
                dst[0]  = vh.x; dst[1]  = vl.x;
                dst[4]  = vh.y; dst[5]  = vl.y;
                dst[8]  = vh.z; dst[9]  = vl.z;
                dst[12] = vh.w; dst[13] = vl.w;
            }
        }
        __syncthreads();

        // ---- compute: 2 k8 steps ----
        #pragma unroll
        for (int kk = 0; kk < 2; kk++) {
            const int kof = kk * 16 + cA4;

            // B fragments: 7 n-tiles, float4 = {b0h, b0l, b1h, b1l}
            float4 bf[7];
            #pragma unroll
            for (int nt = 0; nt < 7; nt++)
                bf[nt] = *(const float4*)&sB[wn * 56 + nt * 8 + rA][kof];

            #pragma unroll
            for (int mt = 0; mt < 2; mt++) {
                const int mrow = wm * 32 + mt * 16 + rA;
                float4 ar0 = *(const float4*)&sA[mrow][kof];      // rows 0-7
                float4 ar8 = *(const float4*)&sA[mrow + 8][kof];  // rows 8-15

                uint32_t a0h = __float_as_uint(ar0.x), a1h = __float_as_uint(ar8.x);
                uint32_t a2h = __float_as_uint(ar0.z), a3h = __float_as_uint(ar8.z);
                uint32_t a0l = __float_as_uint(ar0.y), a1l = __float_as_uint(ar8.y);
                uint32_t a2l = __float_as_uint(ar0.w), a3l = __float_as_uint(ar8.w);

                #pragma unroll
                for (int nt = 0; nt < 7; nt++) {
                    uint32_t b0h = __float_as_uint(bf[nt].x);
                    uint32_t b0l = __float_as_uint(bf[nt].y);
                    uint32_t b1h = __float_as_uint(bf[nt].z);
                    uint32_t b1l = __float_as_uint(bf[nt].w);
                    float* c = acc[mt][nt];
                    mma_tf32(c, a0h, a1h, a2h, a3h, b0h, b1h);  // hi*hi
                    mma_tf32(c, a0h, a1h, a2h, a3h, b0l, b1l);  // hi*lo
                    mma_tf32(c, a0l, a1l, a2l, a3l, b0h, b1h);  // lo*hi
                }
            }
        }
    }

    // ---- epilogue ----
    #pragma unroll
    for (int mt = 0; mt < 2; mt++) {
        const int oc0 = wm * 32 + mt * 16 + rA;
        #pragma unroll
        for (int nt = 0; nt < 7; nt++) {
            const int w = w0 + wn * 56 + nt * 8 + 2 * (lane & 3);
            const float* c = acc[mt][nt];
            float* r0 = out + (oc0 * OH + h) * OW;
            float* r8 = out + ((oc0 + 8) * OH + h) * OW;
            if (w < OW)     { r0[w]     = c[0]; r8[w]     = c[2]; }
            if (w + 1 < OW) { r0[w + 1] = c[1]; r8[w + 1] = c[3]; }
        }
    }
}

// ---------------- launch ----------------
extern "C" void kernel_launch(void* const* d_in, const int* in_sizes, int n_in,
                              void* d_out, int out_size)
{
    const float* x = (const float*)d_in[0];
    const float* k = (const float*)d_in[1];
    if (in_sizes[0] == C_OUT * C_IN * 9) { const float* t = x; x = k; k = t; }
    float* out = (float*)d_out;

    prep_x<<<HW_IN / 64, 256>>>(x);
    prep_w<<<(C_OUT * GK + 255) / 256, 256>>>(k);

    dim3 grid(2, OH);   // 2 N-tiles x 222 rows
    conv_mma_tf32<<<grid, 256>>>(out);
}

// round 14
// speedup vs baseline: 2.3936x; 1.2961x over previous
#include <cuda_runtime.h>
#include <cstdint>

// 3x3 VALID conv via implicit GEMM on mma.sync tf32 (3xTF32 split),
// cp.async double-buffered pipeline.
// x: (64, 224, 224) fp32, kernels: (128, 64, 3, 3) -> out: (128, 222, 222)

#define C_IN   64
#define H_IN   224
#define W_IN   224
#define HW_IN  (H_IN * W_IN)
#define C_OUT  128
#define OH     222
#define OW     222
#define GK     576            // K = C_IN * 9
#define NCH    36             // K chunks of 16
#define WPK    1152           // floats per oc row in packed weights (GK*2)

// ---------------- scratch globals (alloc-free rule) ----------------
// Packed layouts matching the smem fragment interleave exactly:
// 16-channel chunk -> 32 floats; pos(cc) = 16*(q>>1)+2*(q&1)+4*l, q=cc>>2,l=cc&3
// hi at pos, lo at pos+1.
__device__ float g_xp[HW_IN * 128];      // per pixel: 4 chunks x 32 floats
__device__ float g_wp[C_OUT * WPK];      // per oc: 36 chunks x 32 floats

__device__ __forceinline__ int ilv_pos(int cc) {
    int q = cc >> 2, l = cc & 3;
    return 16 * (q >> 1) + 2 * (q & 1) + 4 * l;
}

__device__ __forceinline__ void tf32_split(float v, float& hi, float& lo) {
    uint32_t hb;
    asm("cvt.rna.tf32.f32 %0, %1;" : "=r"(hb) : "f"(v));
    hi = __uint_as_float(hb);
    float r = v - hi;
    uint32_t lb;
    asm("cvt.rna.tf32.f32 %0, %1;" : "=r"(lb) : "f"(r));
    lo = __uint_as_float(lb);
}

// ---------------- prep kernels ----------------
__global__ void prep_x(const float* __restrict__ x) {
    __shared__ float s[64][65];
    int p0 = blockIdx.x * 64;
    for (int i = threadIdx.x; i < 64 * 64; i += 256) {
        int c = i >> 6, j = i & 63;
        s[c][j] = x[c * HW_IN + p0 + j];
    }
    __syncthreads();
    for (int i = threadIdx.x; i < 64 * 64; i += 256) {
        int j = i >> 6, c = i & 63;
        float hi, lo;
        tf32_split(s[c][j], hi, lo);
        int base = (p0 + j) * 128 + (c >> 4) * 32 + ilv_pos(c & 15);
        g_xp[base]     = hi;
        g_xp[base + 1] = lo;
    }
}

__global__ void prep_w(const float* __restrict__ w) {
    int i = blockIdx.x * 256 + threadIdx.x;
    if (i < C_OUT * GK) {
        int oc = i / GK, r = i - oc * GK;
        int blk = r >> 6, c = r & 63;          // k-order: blk = dy*3+dx, then c
        float hi, lo;
        tf32_split(w[oc * GK + c * 9 + blk], hi, lo);
        int base = oc * WPK + (r >> 4) * 32 + ilv_pos(r & 15);
        g_wp[base]     = hi;
        g_wp[base + 1] = lo;
    }
}

// ---------------- main GEMM kernel ----------------
// CTA: 256 thr / 8 warps, tile M=128 x N=112. Warp grid 4(M) x 2(N) -> 32x56.
// K chunk = 16 (32 floats hi/lo). Double-buffered cp.async staging.
#define SROW 48   // smem row stride (floats); data in [0..31]
#define A_FL (128 * SROW)
#define B_FL (112 * SROW)
#define SM_TOTAL ((2 * A_FL + 2 * B_FL) * 4)   // 92160 bytes

#define CPA16(dst, src) asm volatile("cp.async.cg.shared.global [%0], [%1], 16;" :: "r"(dst), "l"(src))
#define CP_COMMIT()     asm volatile("cp.async.commit_group;" ::: "memory")
#define CP_WAIT1()      asm volatile("cp.async.wait_group 1;" ::: "memory")
#define CP_WAIT0()      asm volatile("cp.async.wait_group 0;" ::: "memory")

__device__ __forceinline__ void mma_tf32(float* c, uint32_t a0, uint32_t a1,
                                         uint32_t a2, uint32_t a3,
                                         uint32_t b0, uint32_t b1) {
    asm volatile(
        "mma.sync.aligned.m16n8k8.row.col.f32.tf32.tf32.f32 "
        "{%0,%1,%2,%3}, {%4,%5,%6,%7}, {%8,%9}, {%0,%1,%2,%3};"
        : "+f"(c[0]), "+f"(c[1]), "+f"(c[2]), "+f"(c[3])
        : "r"(a0), "r"(a1), "r"(a2), "r"(a3), "r"(b0), "r"(b1));
}

__device__ __forceinline__ void stage_chunk(int t, uint32_t aS, uint32_t bS,
                                            int h, int w0, int tid) {
    const int blk = t >> 2, s = t & 3;
    const int dy = blk / 3, dx = blk - dy * 3;

    // A: 128 rows x 8 float4 units
    const float* aSrc = g_wp + t * 32;
    #pragma unroll
    for (int u = tid; u < 1024; u += 256) {
        int row = u >> 3, q = u & 7;
        CPA16(aS + (row * SROW + q * 4) * 4, aSrc + row * WPK + q * 4);
    }
    // B: 112 rows x 8 float4 units
    const float* bSrc = g_xp + (h + dy) * (W_IN * 128) + s * 32;
    #pragma unroll
    for (int u = tid; u < 896; u += 256) {
        int n = u >> 3, q = u & 7;
        int wc = w0 + n + dx; if (wc > W_IN - 1) wc = W_IN - 1;
        CPA16(bS + (n * SROW + q * 4) * 4, bSrc + wc * 128 + q * 4);
    }
}

__global__ void __launch_bounds__(256, 2)
conv_mma_tf32(float* __restrict__ out) {
    extern __shared__ float sm[];
    float* sA = sm;                 // [2][128][SROW]
    float* sB = sm + 2 * A_FL;      // [2][112][SROW]

    uint32_t aAddr[2], bAddr[2];
    {
        uint32_t base = (uint32_t)__cvta_generic_to_shared(sm);
        aAddr[0] = base;
        aAddr[1] = base + A_FL * 4;
        bAddr[0] = base + 2 * A_FL * 4;
        bAddr[1] = base + (2 * A_FL + B_FL) * 4;
    }

    const int tid  = threadIdx.x;
    const int lane = tid & 31;
    const int wid  = tid >> 5;
    const int wm   = wid & 3;          // M base 32*wm
    const int wn   = wid >> 2;         // N base 56*wn
    const int h    = blockIdx.y;
    const int w0   = blockIdx.x * 112;

    const int rA  = lane >> 2;         // 0..7
    const int cA4 = (lane & 3) * 4;

    float acc[2][7][4];
    #pragma unroll
    for (int mt = 0; mt < 2; mt++)
        #pragma unroll
        for (int nt = 0; nt < 7; nt++)
            #pragma unroll
            for (int q = 0; q < 4; q++)
                acc[mt][nt][q] = 0.0f;

    // prologue: stage chunk 0
    stage_chunk(0, aAddr[0], bAddr[0], h, w0, tid);
    CP_COMMIT();

    for (int t = 0; t < NCH; t++) {
        const int buf = t & 1;
        if (t + 1 < NCH) {
            stage_chunk(t + 1, aAddr[(t + 1) & 1], bAddr[(t + 1) & 1], h, w0, tid);
            CP_COMMIT();
            CP_WAIT1();     // chunk t complete
        } else {
            CP_WAIT0();
        }
        __syncthreads();

        const float* A = sA + buf * A_FL;
        const float* B = sB + buf * B_FL;

        #pragma unroll
        for (int kk = 0; kk < 2; kk++) {
            const int kof = kk * 16 + cA4;

            float4 bf[7];
            #pragma unroll
            for (int nt = 0; nt < 7; nt++)
                bf[nt] = *(const float4*)&B[(wn * 56 + nt * 8 + rA) * SROW + kof];

            #pragma unroll
            for (int mt = 0; mt < 2; mt++) {
                const int mrow = wm * 32 + mt * 16 + rA;
                float4 ar0 = *(const float4*)&A[mrow * SROW + kof];
                float4 ar8 = *(const float4*)&A[(mrow + 8) * SROW + kof];

                uint32_t a0h = __float_as_uint(ar0.x), a1h = __float_as_uint(ar8.x);
                uint32_t a2h = __float_as_uint(ar0.z), a3h = __float_as_uint(ar8.z);
                uint32_t a0l = __float_as_uint(ar0.y), a1l = __float_as_uint(ar8.y);
                uint32_t a2l = __float_as_uint(ar0.w), a3l = __float_as_uint(ar8.w);

                #pragma unroll
                for (int nt = 0; nt < 7; nt++) {
                    uint32_t b0h = __float_as_uint(bf[nt].x);
                    uint32_t b0l = __float_as_uint(bf[nt].y);
                    uint32_t b1h = __float_as_uint(bf[nt].z);
                    uint32_t b1l = __float_as_uint(bf[nt].w);
                    float* c = acc[mt][nt];
                    mma_tf32(c, a0h, a1h, a2h, a3h, b0h, b1h);  // hi*hi
                    mma_tf32(c, a0h, a1h, a2h, a3h, b0l, b1l);  // hi*lo
                    mma_tf32(c, a0l, a1l, a2l, a3l, b0h, b1h);  // lo*hi
                }
            }
        }
        __syncthreads();   // all reads of buf done before chunk t+2 overwrites it
    }

    // ---- epilogue ----
    #pragma unroll
    for (int mt = 0; mt < 2; mt++) {
        const int oc0 = wm * 32 + mt * 16 + rA;
        #pragma unroll
        for (int nt = 0; nt < 7; nt++) {
            const int w = w0 + wn * 56 + nt * 8 + 2 * (lane & 3);
            const float* c = acc[mt][nt];
            float* r0 = out + (oc0 * OH + h) * OW;
            float* r8 = out + ((oc0 + 8) * OH + h) * OW;
            if (w < OW)     { r0[w]     = c[0]; r8[w]     = c[2]; }
            if (w + 1 < OW) { r0[w + 1] = c[1]; r8[w + 1] = c[3]; }
        }
    }
}

// ---------------- launch ----------------
extern "C" void kernel_launch(void* const* d_in, const int* in_sizes, int n_in,
                              void* d_out, int out_size)
{
    const float* x = (const float*)d_in[0];
    const float* k = (const float*)d_in[1];
    if (in_sizes[0] == C_OUT * C_IN * 9) { const float* t = x; x = k; k = t; }
    float* out = (float*)d_out;

    cudaFuncSetAttribute(conv_mma_tf32,
                         cudaFuncAttributeMaxDynamicSharedMemorySize, SM_TOTAL);

    prep_x<<<HW_IN / 64, 256>>>(x);
    prep_w<<<(C_OUT * GK + 255) / 256, 256>>>(k);

    dim3 grid(2, OH);   // 2 N-tiles x 222 rows
    conv_mma_tf32<<<grid, 256, SM_TOTAL>>>(out);
}

// round 16
// speedup vs baseline: 2.4903x; 1.0404x over previous
#include <cuda_runtime.h>
#include <cuda_bf16.h>
#include <cstdint>

// 3x3 VALID conv via implicit GEMM, bf16 double-split (3 products) on
// mma.sync.m16n8k16, cp.async double-buffered pipeline, ldmatrix fragments.
// x: (64, 224, 224) fp32, kernels: (128, 64, 3, 3) -> out: (128, 222, 222)

#define C_IN   64
#define H_IN   224
#define W_IN   224
#define HW_IN  (H_IN * W_IN)
#define C_OUT  128
#define OH     222
#define OW     222
#define GK     576            // K = C_IN * 9
#define NCH    36             // K chunks of 16

// ---------------- scratch globals (alloc-free rule) ----------------
// Per pixel: 4 chunks x [hi 16 bf16 | mid 16 bf16] = 4 x 64B = 256B.
__device__ __align__(16) unsigned char g_xp[HW_IN * 256];
// Per oc: 36 chunks x 64B = 2304B.
__device__ __align__(16) unsigned char g_wp[C_OUT * 2304];

__device__ __forceinline__ void bf16_split(float v, __nv_bfloat16& hi, __nv_bfloat16& mi) {
    hi = __float2bfloat16_rn(v);
    mi = __float2bfloat16_rn(v - __bfloat162float(hi));
}

// ---------------- prep kernels ----------------
__global__ void prep_x(const float* __restrict__ x) {
    __shared__ float s[64][65];
    int p0 = blockIdx.x * 64;
    for (int i = threadIdx.x; i < 64 * 64; i += 256) {
        int c = i >> 6, j = i & 63;
        s[c][j] = x[c * HW_IN + p0 + j];
    }
    __syncthreads();
    // one thread per (pixel, 16-channel chunk): writes 64B contiguous
    int t = threadIdx.x;
    int j = t >> 2, c4 = t & 3;
    __nv_bfloat16 hi[16], mi[16];
    #pragma unroll
    for (int cc = 0; cc < 16; cc++)
        bf16_split(s[c4 * 16 + cc][j], hi[cc], mi[cc]);
    uint4* dst = (uint4*)(g_xp + (size_t)(p0 + j) * 256 + c4 * 64);
    dst[0] = *(uint4*)&hi[0];
    dst[1] = *(uint4*)&hi[8];
    dst[2] = *(uint4*)&mi[0];
    dst[3] = *(uint4*)&mi[8];
}

__global__ void prep_w(const float* __restrict__ w) {
    int t = blockIdx.x * 256 + threadIdx.x;   // (oc, chunk)
    if (t >= C_OUT * NCH) return;
    int oc = t / NCH, ch = t - oc * NCH;
    int blk = ch >> 2;                 // dy*3+dx
    int cbase = (ch & 3) * 16;
    __nv_bfloat16 hi[16], mi[16];
    #pragma unroll
    for (int cc = 0; cc < 16; cc++)
        bf16_split(w[oc * GK + (cbase + cc) * 9 + blk], hi[cc], mi[cc]);
    uint4* dst = (uint4*)(g_wp + (size_t)oc * 2304 + ch * 64);
    dst[0] = *(uint4*)&hi[0];
    dst[1] = *(uint4*)&hi[8];
    dst[2] = *(uint4*)&mi[0];
    dst[3] = *(uint4*)&mi[8];
}

// ---------------- main GEMM kernel ----------------
// CTA: 256 thr / 8 warps, tile M=128 x N=112. Warp grid 4(M) x 2(N) -> 32x56.
// K chunk = 16. Smem: bf16 planes, row stride 48B (conflict-free ldmatrix).
// Buffer: [A hi 128*48][A mid 128*48][B hi 112*48][B mid 112*48] = 23040B, x2.
#define ARS   48
#define APL   (128 * ARS)          // 6144
#define BPL   (112 * ARS)          // 5376
#define BUFB  (2 * APL + 2 * BPL)  // 23040

#define CPA16(dst, src) asm volatile("cp.async.cg.shared.global [%0], [%1], 16;" :: "r"(dst), "l"(src))
#define CP_COMMIT()     asm volatile("cp.async.commit_group;" ::: "memory")
#define CP_WAIT1()      asm volatile("cp.async.wait_group 1;" ::: "memory")
#define CP_WAIT0()      asm volatile("cp.async.wait_group 0;" ::: "memory")

#define LDSM_X4(r0, r1, r2, r3, a)                                              \
    asm volatile("ldmatrix.sync.aligned.m8n8.x4.shared.b16 {%0,%1,%2,%3}, [%4];"\
        : "=r"(r0), "=r"(r1), "=r"(r2), "=r"(r3) : "r"(a))
#define LDSM_X2(r0, r1, a)                                                      \
    asm volatile("ldmatrix.sync.aligned.m8n8.x2.shared.b16 {%0,%1}, [%2];"      \
        : "=r"(r0), "=r"(r1) : "r"(a))

__device__ __forceinline__ void mma_bf16(float* c, const uint32_t* a,
                                         uint32_t b0, uint32_t b1) {
    asm volatile(
        "mma.sync.aligned.m16n8k16.row.col.f32.bf16.bf16.f32 "
        "{%0,%1,%2,%3}, {%4,%5,%6,%7}, {%8,%9}, {%0,%1,%2,%3};"
        : "+f"(c[0]), "+f"(c[1]), "+f"(c[2]), "+f"(c[3])
        : "r"(a[0]), "r"(a[1]), "r"(a[2]), "r"(a[3]), "r"(b0), "r"(b1));
}

__device__ __forceinline__ void stage_chunk(int t, uint32_t sBuf,
                                            int h, int w0, int tid) {
    const int blk = t >> 2, s = t & 3;
    const int dy = blk / 3, dx = blk - dy * 3;

    // A: 128 rows x 4 x 16B  (hi halves q=0,1 ; mid halves q=2,3)
    const unsigned char* aSrc = g_wp + t * 64;
    #pragma unroll
    for (int u = tid; u < 512; u += 256) {
        int row = u >> 2, q = u & 3, pl = q >> 1, hf = q & 1;
        CPA16(sBuf + pl * APL + row * ARS + hf * 16,
              aSrc + (size_t)row * 2304 + q * 16);
    }
    // B: 112 rows x 4 x 16B
    const unsigned char* bSrc = g_xp + s * 64;
    #pragma unroll
    for (int u = tid; u < 448; u += 256) {
        int n = u >> 2, q = u & 3, pl = q >> 1, hf = q & 1;
        int wc = w0 + n + dx; if (wc > W_IN - 1) wc = W_IN - 1;
        CPA16(sBuf + 2 * APL + pl * BPL + n * ARS + hf * 16,
              bSrc + (size_t)((h + dy) * W_IN + wc) * 256 + q * 16);
    }
}

__global__ void __launch_bounds__(256, 2)
conv_mma_bf16(float* __restrict__ out) {
    __shared__ __align__(16) unsigned char sm[2 * BUFB];
    const uint32_t sBase = (uint32_t)__cvta_generic_to_shared(sm);

    const int tid  = threadIdx.x;
    const int lane = tid & 31;
    const int wid  = tid >> 5;
    const int wm   = wid & 3;          // M base 32*wm
    const int wn   = wid >> 2;         // N base 56*wn
    const int h    = blockIdx.y;
    const int w0   = blockIdx.x * 112;

    // ldmatrix lane addressing: g = matrix index, rr = row within matrix
    const int g  = lane >> 3;
    const int rr = lane & 7;
    // A x4: m0 rows0-7 k0-7, m1 rows8-15 k0-7, m2 rows0-7 k8-15, m3 rows8-15 k8-15
    const uint32_t aLane = (uint32_t)((wm * 32 + (g & 1) * 8 + rr) * ARS + (g >> 1) * 16);
    // B x4 (nt pair): m0 nt rows k0-7, m1 nt k8-15, m2 nt+1 k0-7, m3 nt+1 k8-15
    const uint32_t bLane = (uint32_t)((wn * 56 + (g >> 1) * 8 + rr) * ARS + (g & 1) * 16);
    // B x2 (nt=6): m0 k0-7, m1 k8-15
    const uint32_t bLane2 = (uint32_t)((wn * 56 + 48 + rr) * ARS + ((lane >> 3) & 1) * 16);

    float acc[2][7][4];
    #pragma unroll
    for (int mt = 0; mt < 2; mt++)
        #pragma unroll
        for (int nt = 0; nt < 7; nt++)
            #pragma unroll
            for (int q = 0; q < 4; q++)
                acc[mt][nt][q] = 0.0f;

    stage_chunk(0, sBase, h, w0, tid);
    CP_COMMIT();

    for (int t = 0; t < NCH; t++) {
        const uint32_t buf = sBase + (uint32_t)(t & 1) * BUFB;
        if (t + 1 < NCH) {
            stage_chunk(t + 1, sBase + (uint32_t)((t + 1) & 1) * BUFB, h, w0, tid);
            CP_COMMIT();
            CP_WAIT1();
        } else {
            CP_WAIT0();
        }
        __syncthreads();

        // ---- load fragments ----
        uint32_t ah[2][4], am[2][4];
        #pragma unroll
        for (int mt = 0; mt < 2; mt++) {
            uint32_t off = aLane + (uint32_t)(mt * 16 * ARS);
            LDSM_X4(ah[mt][0], ah[mt][1], ah[mt][2], ah[mt][3], buf + off);
            LDSM_X4(am[mt][0], am[mt][1], am[mt][2], am[mt][3], buf + APL + off);
        }
        uint32_t bh[7][2], bm[7][2];
        const uint32_t bhBase = buf + 2 * APL;
        const uint32_t bmBase = bhBase + BPL;
        #pragma unroll
        for (int p = 0; p < 3; p++) {
            uint32_t off = bLane + (uint32_t)(p * 16 * ARS);
            LDSM_X4(bh[2*p][0], bh[2*p][1], bh[2*p+1][0], bh[2*p+1][1], bhBase + off);
            LDSM_X4(bm[2*p][0], bm[2*p][1], bm[2*p+1][0], bm[2*p+1][1], bmBase + off);
        }
        LDSM_X2(bh[6][0], bh[6][1], bhBase + bLane2);
        LDSM_X2(bm[6][0], bm[6][1], bmBase + bLane2);

        // ---- 42 mma ----
        #pragma unroll
        for (int mt = 0; mt < 2; mt++)
            #pragma unroll
            for (int nt = 0; nt < 7; nt++) {
                float* c = acc[mt][nt];
                mma_bf16(c, ah[mt], bh[nt][0], bh[nt][1]);  // hi*hi
                mma_bf16(c, ah[mt], bm[nt][0], bm[nt][1]);  // hi*mid
                mma_bf16(c, am[mt], bh[nt][0], bh[nt][1]);  // mid*hi
            }

        __syncthreads();
    }

    // ---- epilogue ----
    const int rA = lane >> 2;
    #pragma unroll
    for (int mt = 0; mt < 2; mt++) {
        const int oc0 = wm * 32 + mt * 16 + rA;
        #pragma unroll
        for (int nt = 0; nt < 7; nt++) {
            const int w = w0 + wn * 56 + nt * 8 + 2 * (lane & 3);
            const float* c = acc[mt][nt];
            float* r0 = out + (oc0 * OH + h) * OW;
            float* r8 = out + ((oc0 + 8) * OH + h) * OW;
            if (w < OW)     { r0[w]     = c[0]; r8[w]     = c[2]; }
            if (w + 1 < OW) { r0[w + 1] = c[1]; r8[w + 1] = c[3]; }
        }
    }
}

// ---------------- launch ----------------
extern "C" void kernel_launch(void* const* d_in, const int* in_sizes, int n_in,
                              void* d_out, int out_size)
{
    const float* x = (const float*)d_in[0];
    const float* k = (const float*)d_in[1];
    if (in_sizes[0] == C_OUT * C_IN * 9) { const float* t = x; x = k; k = t; }
    float* out = (float*)d_out;

    prep_x<<<HW_IN / 64, 256>>>(x);
    prep_w<<<(C_OUT * NCH + 255) / 256, 256>>>(k);

    dim3 grid(2, OH);   // 2 N-tiles x 222 rows
    conv_mma_bf16<<<grid, 256>>>(out);
}